// round 16
// baseline (speedup 1.0000x reference)
#include <cuda_runtime.h>
#include <cuda_fp16.h>
#include <cstdint>

// ===========================================================================
// Problem constants
// ===========================================================================
#define Nn   4
#define Cc   512
#define Ss   2048
#define Hh   8
#define CH   4096
#define CTXD 512
#define ZTOT (Nn * Hh * Ss)

#define SCALE2 0.044194173824159216f   // 512^-0.5
#define LNEPS  1e-5f

// ===========================================================================
// PTX helpers
// ===========================================================================
__device__ __forceinline__ uint32_t smem_to_u32(const void* smem_ptr) {
    uint32_t addr;
    asm("{ .reg .u64 tmp; cvta.to.shared.u64 tmp, %1; cvt.u32.u64 %0, tmp; }"
        : "=r"(addr) : "l"(smem_ptr));
    return addr;
}

__device__ __forceinline__ void cpa16(uint32_t s, const void* g) {
    asm volatile("cp.async.cg.shared.global [%0], [%1], 16;" :: "r"(s), "l"(g));
}
#define CP_COMMIT() asm volatile("cp.async.commit_group;" ::: "memory")
#define CP_WAIT(n)  asm volatile("cp.async.wait_group %0;" :: "n"(n) : "memory")

__device__ __forceinline__ void ldm_x4(uint32_t* r, uint32_t saddr) {
    asm volatile("ldmatrix.sync.aligned.m8n8.x4.shared.b16 {%0,%1,%2,%3}, [%4];"
        : "=r"(r[0]), "=r"(r[1]), "=r"(r[2]), "=r"(r[3]) : "r"(saddr));
}

__device__ __forceinline__ void mma16816_f16(uint32_t* c, const uint32_t* a,
                                             uint32_t b0, uint32_t b1) {
    asm volatile(
        "mma.sync.aligned.m16n8k16.row.col.f16.f16.f16.f16 "
        "{%0,%1},{%2,%3,%4,%5},{%6,%7},{%0,%1};"
        : "+r"(c[0]), "+r"(c[1])
        : "r"(a[0]), "r"(a[1]), "r"(a[2]), "r"(a[3]), "r"(b0), "r"(b1));
}

__device__ __forceinline__ uint32_t packh2(float a, float b) {
    __half2 h = __floats2half2_rn(a, b);
    return *(uint32_t*)&h;
}

// ===========================================================================
// Scratch
// ===========================================================================
__device__ __half g_wq [(size_t)CH * Cc];
__device__ __half g_wkv[(size_t)2 * CH * CTXD];
__device__ __half g_wo [(size_t)Cc * CH];
__device__ __half g_xnT [(size_t)Nn * Ss * Cc];       // [n][s][c]
__device__ __half g_ctxT[(size_t)Nn * Ss * CTXD];     // [n][s][d]
__device__ __half g_q  [(size_t)Nn * Ss * CH];        // [n][s][h*512+c]
__device__ __half g_k  [(size_t)Nn * Ss * CH];        // [n][s][h*512+c]
__device__ __half g_vb [(size_t)Nn * CH * Ss];        // [n][o][s]
__device__ __half g_attp[(size_t)Nn * Hh * Ss * Ss];  // exp(scores)
__device__ float  g_rowsum[ZTOT];
__device__ __half g_yT [(size_t)Nn * Ss * CH];        // [n][s][h*512+c]
__device__ float g_part[Nn * 128 * 2];
__device__ float g_stats[Nn * 2];

// ===========================================================================
// LayerNorm stats + misc prep
// ===========================================================================
__global__ void ln_part_kernel(const float* __restrict__ x) {
    int n = blockIdx.y, b = blockIdx.x;
    const int chunk = (Cc * Ss) / 128;
    const float4* p4 = (const float4*)(x + (size_t)n * Cc * Ss + (size_t)b * chunk);
    float s = 0.f, s2 = 0.f;
    for (int i = threadIdx.x; i < chunk / 4; i += 256) {
        float4 v = p4[i];
        s  += v.x + v.y + v.z + v.w;
        s2 += v.x * v.x + v.y * v.y + v.z * v.z + v.w * v.w;
    }
    __shared__ float sh0[256], sh1[256];
    sh0[threadIdx.x] = s; sh1[threadIdx.x] = s2;
    __syncthreads();
    for (int o = 128; o > 0; o >>= 1) {
        if (threadIdx.x < o) {
            sh0[threadIdx.x] += sh0[threadIdx.x + o];
            sh1[threadIdx.x] += sh1[threadIdx.x + o];
        }
        __syncthreads();
    }
    if (threadIdx.x == 0) {
        g_part[(n * 128 + b) * 2 + 0] = sh0[0];
        g_part[(n * 128 + b) * 2 + 1] = sh1[0];
    }
}

__global__ void ln_fin_kernel() {
    int n = blockIdx.x, t = threadIdx.x;
    float s  = g_part[(n * 128 + t) * 2 + 0];
    float s2 = g_part[(n * 128 + t) * 2 + 1];
    __shared__ float sh0[128], sh1[128];
    sh0[t] = s; sh1[t] = s2;
    __syncthreads();
    for (int o = 64; o > 0; o >>= 1) {
        if (t < o) { sh0[t] += sh0[t + o]; sh1[t] += sh1[t + o]; }
        __syncthreads();
    }
    if (t == 0) {
        const float inv = 1.0f / (float)(Cc * Ss);
        float mu  = sh0[0] * inv;
        float var = sh1[0] * inv - mu * mu;
        g_stats[n * 2 + 0] = mu;
        g_stats[n * 2 + 1] = rsqrtf(var + LNEPS);
    }
}

__global__ void zero_rowsum_kernel() {
    int i = blockIdx.x * 256 + threadIdx.x;
    ((float4*)g_rowsum)[i] = make_float4(0.f, 0.f, 0.f, 0.f);
}

template<bool LN>
__global__ void prepT_kernel(const float* __restrict__ X, __half* __restrict__ O,
                             const float* __restrict__ gamma, const float* __restrict__ beta,
                             int R, int S)
{
    __shared__ float tile[32][33];
    int z = blockIdx.z;
    int s0 = blockIdx.x * 32, r0 = blockIdx.y * 32;
    const float* Xb = X + (size_t)z * R * S;
    __half* Ob = O + (size_t)z * R * S;
    float mu = 0.f, rs = 0.f;
    if (LN) { mu = g_stats[z * 2 + 0]; rs = g_stats[z * 2 + 1]; }
    int tx = threadIdx.x, ty = threadIdx.y;
#pragma unroll
    for (int i = 0; i < 32; i += 8) {
        int r = r0 + ty + i;
        float val = Xb[(size_t)r * S + s0 + tx];
        if (LN) {
            float g = gamma[r] * rs;
            val = val * g + (beta[r] - mu * g);
        }
        tile[ty + i][tx] = val;
    }
    __syncthreads();
#pragma unroll
    for (int i = 0; i < 32; i += 8) {
        int s = s0 + ty + i;
        Ob[(size_t)s * R + r0 + tx] = __float2half_rn(tile[tx][ty + i]);
    }
}

// Merged fp32->fp16 conversion of all three weight tensors (one launch).
__global__ void f2h3_kernel(const float* __restrict__ X0, __half* __restrict__ O0,
                            const float* __restrict__ X1, __half* __restrict__ O1,
                            const float* __restrict__ X2, __half* __restrict__ O2)
{
    int b = blockIdx.x;
    const float* X; __half* O; int i;
    if (b < 2048)      { X = X0; O = O0; i = b * 256 + threadIdx.x; }
    else if (b < 6144) { X = X1; O = O1; i = (b - 2048) * 256 + threadIdx.x; }
    else               { X = X2; O = O2; i = (b - 6144) * 256 + threadIdx.x; }
    float4 v = ((const float4*)X)[i];
    __half2* o = (__half2*)O + (size_t)i * 2;
    o[0] = __floats2half2_rn(v.x, v.y);
    o[1] = __floats2half2_rn(v.z, v.w);
}

// ===========================================================================
// 128x128 fp16-acc GEMM: 64x32 warp tiles, BK=32, 2-stage cp.async,
// __launch_bounds__(256,4) -> 4 CTAs/SM = 32 warps (occupancy experiment).
// A: [M][K] K-major. B: [N][K] K-major.
// EPI 0: exp(d*SCALE2) fp16 -> attp[z][m][j] + rowsums (zn=z>>3, zh=z&7)
// EPI 1: row-bias fp16   -> vb [z][m][j]             (V; z = n)
// EPI 2: MERGED Q/K (z in [0,8): sel=z>>2, n=z&3): col-bias fp16
//        -> (sel? Cv2 : Cv)[n][s][4096col]
// EPI 3: /rowsum[m] fp16 -> yT [zn][m][zh*512+col]   (y; zn=z>>3, zh=z&7)
// EPI 4: fp32 +bias[m] +residual -> out [z][m][j]    (out projection; z = n)
// ===========================================================================
#define ROWB   80
#define STG128 20480     // (128 + 128) * 80 per stage
#define SMEM_C 40960     // 2 stages

template<int EPI>
__global__ __launch_bounds__(256, 4) void hg128(
    const __half* __restrict__ A, size_t lda, size_t aSN, size_t aSH,
    const __half* __restrict__ B, size_t ldb, size_t bSN, size_t bSH,
    void* __restrict__ Cv,
    const float* __restrict__ bias,
    const float* __restrict__ resid,
    const __half* __restrict__ A2, const __half* __restrict__ B2,
    const float* __restrict__ bias2, void* __restrict__ Cv2,
    float* __restrict__ rsum,
    int nt)
{
    extern __shared__ __align__(1024) char smem[];
    const uint32_t sb = smem_to_u32(smem);

    const int tid  = threadIdx.x;
    const int warp = tid >> 5;
    const int lane = tid & 31;
    const int wm = warp >> 2;       // 0..1
    const int wn = warp & 3;        // 0..3
    const int z  = blockIdx.z;
    const int m0 = blockIdx.y * 128;
    const int j0 = blockIdx.x * 128;

    // batch decode (+ Q/K merge for EPI 2)
    const __half* Abase = A;
    const __half* Bbase = B;
    const float*  biasp = bias;
    void*         Cp    = Cv;
    int zn, zh;
    if (EPI == 2) {
        zn = 0; zh = z & 3;
        if (z >> 2) { Abase = A2; Bbase = B2; biasp = bias2; Cp = Cv2; }
    } else if (EPI == 0 || EPI == 3) {
        zn = z >> 3; zh = z & 7;
    } else {
        zn = 0; zh = z;
    }

    const __half* Ab = Abase + (size_t)zn * aSN + (size_t)zh * aSH
                             + (size_t)(m0 + (tid >> 1)) * lda;
    const __half* Bb = Bbase + (size_t)zn * bSN + (size_t)zh * bSH
                             + (size_t)(j0 + (tid >> 1)) * ldb;

    const uint32_t sA = sb + (uint32_t)(tid >> 1) * ROWB + (uint32_t)(tid & 1) * 32;
    const uint32_t sB = sA + 10240;
    const int gseg = (tid & 1) * 16;

    auto prefetch = [&](int kt, int buf) {
        uint32_t so = (uint32_t)buf * STG128;
        const __half* ga = Ab + (size_t)kt * 32 + gseg;
        const __half* gb = Bb + (size_t)kt * 32 + gseg;
        cpa16(sA + so,      ga);
        cpa16(sA + so + 16, ga + 8);
        cpa16(sB + so,      gb);
        cpa16(sB + so + 16, gb + 8);
    };

    uint32_t acch[4][4][2];
#pragma unroll
    for (int i = 0; i < 4; i++)
#pragma unroll
        for (int j = 0; j < 4; j++) { acch[i][j][0] = 0u; acch[i][j][1] = 0u; }

    const int lrow = lane & 15;
    const int lcolb = (lane >> 4) * 16;

    prefetch(0, 0); CP_COMMIT();

    for (int t = 0; t < nt; t++) {
        CP_WAIT(0);
        __syncthreads();            // buf t&1 ready; all warps done reading buf (t+1)&1
        if (t + 1 < nt) { prefetch(t + 1, (t + 1) & 1); CP_COMMIT(); }

        uint32_t aB = sb + (uint32_t)((t & 1) * STG128);
        uint32_t bB = aB + 10240;
#pragma unroll
        for (int ks = 0; ks < 2; ks++) {
            uint32_t colb = (uint32_t)(ks * 32 + lcolb);
            uint32_t a[4][4], bf[2][4];
#pragma unroll
            for (int i = 0; i < 4; i++)
                ldm_x4(a[i], aB + (uint32_t)(wm * 64 + i * 16 + lrow) * ROWB + colb);
#pragma unroll
            for (int p = 0; p < 2; p++)
                ldm_x4(bf[p], bB + (uint32_t)(wn * 32 + p * 16 + lrow) * ROWB + colb);
#pragma unroll
            for (int i = 0; i < 4; i++) {
#pragma unroll
                for (int p = 0; p < 2; p++) {
                    mma16816_f16(acch[i][p * 2 + 0], a[i], bf[p][0], bf[p][2]);
                    mma16816_f16(acch[i][p * 2 + 1], a[i], bf[p][1], bf[p][3]);
                }
            }
        }
    }

    const int rq = lane >> 2;
    const int cq = (lane & 3) * 2;

#pragma unroll
    for (int i = 0; i < 4; i++) {
        const int ra = m0 + wm * 64 + i * 16 + rq;

        if (EPI == 0) {          // exp + rowsum -> attp [z][m][j]
            __half* d0 = (__half*)Cp + (size_t)z * Ss * Ss + (size_t)ra * Ss + j0;
            __half* d1 = d0 + 8 * Ss;
            float s0 = 0.f, s1 = 0.f;
#pragma unroll
            for (int j = 0; j < 4; j++) {
                int col = wn * 32 + (j >> 1) * 16 + (j & 1) * 8 + cq;
                float2 v0 = __half22float2(*(const __half2*)&acch[i][j][0]);
                float2 v1 = __half22float2(*(const __half2*)&acch[i][j][1]);
                float e0 = __expf(v0.x * SCALE2), e1 = __expf(v0.y * SCALE2);
                float e2 = __expf(v1.x * SCALE2), e3 = __expf(v1.y * SCALE2);
                s0 += e0 + e1; s1 += e2 + e3;
                *(uint32_t*)(d0 + col) = packh2(e0, e1);
                *(uint32_t*)(d1 + col) = packh2(e2, e3);
            }
            s0 += __shfl_xor_sync(0xFFFFFFFF, s0, 1);
            s0 += __shfl_xor_sync(0xFFFFFFFF, s0, 2);
            s1 += __shfl_xor_sync(0xFFFFFFFF, s1, 1);
            s1 += __shfl_xor_sync(0xFFFFFFFF, s1, 2);
            if ((lane & 3) == 0) {
                atomicAdd(rsum + (size_t)z * Ss + ra,     s0);
                atomicAdd(rsum + (size_t)z * Ss + ra + 8, s1);
            }
        } else if (EPI == 1) {   // V: row bias -> vb [z][m][j]
            float b0 = biasp[ra], b1 = biasp[ra + 8];
            __half* d0 = (__half*)Cp + (size_t)zh * CH * Ss + (size_t)ra * Ss + j0;
            __half* d1 = d0 + 8 * Ss;
#pragma unroll
            for (int j = 0; j < 4; j++) {
                int col = wn * 32 + (j >> 1) * 16 + (j & 1) * 8 + cq;
                float2 v0 = __half22float2(*(const __half2*)&acch[i][j][0]);
                float2 v1 = __half22float2(*(const __half2*)&acch[i][j][1]);
                *(uint32_t*)(d0 + col) = packh2(v0.x + b0, v0.y + b0);
                *(uint32_t*)(d1 + col) = packh2(v1.x + b1, v1.y + b1);
            }
        } else if (EPI == 2) {   // merged Q/K: col bias -> [n][s][4096]
            __half* d0 = (__half*)Cp + (size_t)zh * Ss * CH + (size_t)ra * CH + j0;
            __half* d1 = d0 + 8 * CH;
#pragma unroll
            for (int j = 0; j < 4; j++) {
                int col = wn * 32 + (j >> 1) * 16 + (j & 1) * 8 + cq;
                float2 bb = *(const float2*)&biasp[j0 + col];
                float2 v0 = __half22float2(*(const __half2*)&acch[i][j][0]);
                float2 v1 = __half22float2(*(const __half2*)&acch[i][j][1]);
                *(uint32_t*)(d0 + col) = packh2(v0.x + bb.x, v0.y + bb.y);
                *(uint32_t*)(d1 + col) = packh2(v1.x + bb.x, v1.y + bb.y);
            }
        } else if (EPI == 3) {   // y: /rowsum -> yT [zn][m][zh*512+col]
            float inv0 = 1.0f / rsum[(size_t)z * Ss + ra];
            float inv1 = 1.0f / rsum[(size_t)z * Ss + ra + 8];
            __half* d0 = (__half*)Cp + (size_t)zn * Ss * CH + (size_t)ra * CH + zh * 512 + j0;
            __half* d1 = d0 + 8 * CH;
#pragma unroll
            for (int j = 0; j < 4; j++) {
                int col = wn * 32 + (j >> 1) * 16 + (j & 1) * 8 + cq;
                float2 v0 = __half22float2(*(const __half2*)&acch[i][j][0]);
                float2 v1 = __half22float2(*(const __half2*)&acch[i][j][1]);
                *(uint32_t*)(d0 + col) = packh2(v0.x * inv0, v0.y * inv0);
                *(uint32_t*)(d1 + col) = packh2(v1.x * inv1, v1.y * inv1);
            }
        } else {                 // EPI 4: out fp32 +bias +residual
            float b0 = biasp[ra], b1 = biasp[ra + 8];
            size_t off0 = (size_t)zh * Cc * Ss + (size_t)ra * Ss + j0;
            size_t off1 = off0 + 8 * Ss;
            float* dst = (float*)Cp;
#pragma unroll
            for (int j = 0; j < 4; j++) {
                int col = wn * 32 + (j >> 1) * 16 + (j & 1) * 8 + cq;
                float2 v0 = __half22float2(*(const __half2*)&acch[i][j][0]);
                float2 v1 = __half22float2(*(const __half2*)&acch[i][j][1]);
                float2 r0 = *(const float2*)(resid + off0 + col);
                float2 r1 = *(const float2*)(resid + off1 + col);
                *(float2*)(dst + off0 + col) = make_float2(v0.x + b0 + r0.x, v0.y + b0 + r0.y);
                *(float2*)(dst + off1 + col) = make_float2(v1.x + b1 + r1.x, v1.y + b1 + r1.y);
            }
        }
    }
}

// ===========================================================================
// Host
// ===========================================================================
extern "C" void kernel_launch(void* const* d_in, const int* in_sizes, int n_in,
                              void* d_out, int out_size) {
    const float* input   = (const float*)d_in[0];
    const float* context = (const float*)d_in[1];
    const float* gamma   = (const float*)d_in[2];
    const float* beta    = (const float*)d_in[3];
    const float* Wq      = (const float*)d_in[4];
    const float* bq      = (const float*)d_in[5];
    const float* Wkv     = (const float*)d_in[6];
    const float* bkv     = (const float*)d_in[7];
    const float* Wo      = (const float*)d_in[8];
    const float* bo      = (const float*)d_in[9];
    float* out = (float*)d_out;

    static int configured = 0;
    if (!configured) {
        cudaFuncSetAttribute(hg128<0>, cudaFuncAttributeMaxDynamicSharedMemorySize, SMEM_C);
        cudaFuncSetAttribute(hg128<1>, cudaFuncAttributeMaxDynamicSharedMemorySize, SMEM_C);
        cudaFuncSetAttribute(hg128<2>, cudaFuncAttributeMaxDynamicSharedMemorySize, SMEM_C);
        cudaFuncSetAttribute(hg128<3>, cudaFuncAttributeMaxDynamicSharedMemorySize, SMEM_C);
        cudaFuncSetAttribute(hg128<4>, cudaFuncAttributeMaxDynamicSharedMemorySize, SMEM_C);
        configured = 1;
    }

    __half *wq_h, *wkv_h, *wo_h, *xnT, *ctxT, *qp, *kp, *vb, *attp, *yT;
    float *rsum;
    cudaGetSymbolAddress((void**)&wq_h,  g_wq);
    cudaGetSymbolAddress((void**)&wkv_h, g_wkv);
    cudaGetSymbolAddress((void**)&wo_h,  g_wo);
    cudaGetSymbolAddress((void**)&xnT,   g_xnT);
    cudaGetSymbolAddress((void**)&ctxT,  g_ctxT);
    cudaGetSymbolAddress((void**)&qp,    g_q);
    cudaGetSymbolAddress((void**)&kp,    g_k);
    cudaGetSymbolAddress((void**)&vb,    g_vb);
    cudaGetSymbolAddress((void**)&attp,  g_attp);
    cudaGetSymbolAddress((void**)&rsum,  g_rowsum);
    cudaGetSymbolAddress((void**)&yT,    g_yT);

    // 0: merged weight conversion
    f2h3_kernel<<<8192, 256>>>(Wq, wq_h, Wkv, wkv_h, Wo, wo_h);
    // 1: context transpose
    prepT_kernel<false><<<dim3(Ss / 32, CTXD / 32, Nn), dim3(32, 8)>>>(
        context, ctxT, nullptr, nullptr, CTXD, Ss);
    // 2: LN partials
    ln_part_kernel<<<dim3(128, Nn), 256>>>(input);

    // 3 (PROFILED): V = Wv @ ctx + bv -> vb [n][o][s]
    hg128<1><<<dim3(Ss / 128, CH / 128, Nn), 256, SMEM_C>>>(
        wkv_h + (size_t)CH * CTXD, CTXD, 0, 0,
        ctxT, CTXD, 0, (size_t)Ss * CTXD,
        vb, bkv + CH, nullptr,
        nullptr, nullptr, nullptr, nullptr, nullptr, CTXD / 32);

    ln_fin_kernel<<<Nn, 128>>>();
    prepT_kernel<true><<<dim3(Ss / 32, Cc / 32, Nn), dim3(32, 8)>>>(
        input, xnT, gamma, beta, Cc, Ss);
    zero_rowsum_kernel<<<64, 256>>>();

    // merged Q + K projections: z in [0,4) -> Q, z in [4,8) -> K
    hg128<2><<<dim3(CH / 128, Ss / 128, 2 * Nn), 256, SMEM_C>>>(
        xnT, Cc, 0, (size_t)Ss * Cc,
        wq_h, Cc, 0, 0,
        qp, bq, nullptr,
        ctxT, wkv_h, bkv, kp,
        nullptr, Cc / 32);

    // scores: exp(q·k^T * SCALE2) -> attp[z][q][k] + rowsums
    hg128<0><<<dim3(Ss / 128, Ss / 128, Nn * Hh), 256, SMEM_C>>>(
        qp, CH, (size_t)Ss * CH, 512,
        kp, CH, (size_t)Ss * CH, 512,
        attp, nullptr, nullptr,
        nullptr, nullptr, nullptr, nullptr, rsum, Cc / 32);

    // y = (attp @ v^T) / rowsum -> yT [n][s][h*512+c]
    hg128<3><<<dim3(Cc / 128, Ss / 128, Nn * Hh), 256, SMEM_C>>>(
        attp, Ss, (size_t)8 * Ss * Ss, (size_t)Ss * Ss,
        vb, Ss, (size_t)CH * Ss, (size_t)512 * Ss,
        yT, nullptr, nullptr,
        nullptr, nullptr, nullptr, nullptr, rsum, Ss / 32);

    // out = Wo @ y + bo + input
    hg128<4><<<dim3(Ss / 128, Cc / 128, Nn), 256, SMEM_C>>>(
        wo_h, CH, 0, 0,
        yT, CH, 0, (size_t)Ss * CH,
        out, bo, input,
        nullptr, nullptr, nullptr, nullptr, nullptr, CH / 32);
}

// round 17
// speedup vs baseline: 1.0270x; 1.0270x over previous
#include <cuda_runtime.h>
#include <cuda_fp16.h>
#include <cstdint>

// ===========================================================================
// Problem constants
// ===========================================================================
#define Nn   4
#define Cc   512
#define Ss   2048
#define Hh   8
#define CH   4096
#define CTXD 512
#define ZTOT (Nn * Hh * Ss)

#define SCALE2 0.044194173824159216f   // 512^-0.5
#define LNEPS  1e-5f

// ===========================================================================
// PTX helpers
// ===========================================================================
__device__ __forceinline__ uint32_t smem_to_u32(const void* smem_ptr) {
    uint32_t addr;
    asm("{ .reg .u64 tmp; cvta.to.shared.u64 tmp, %1; cvt.u32.u64 %0, tmp; }"
        : "=r"(addr) : "l"(smem_ptr));
    return addr;
}

__device__ __forceinline__ void cpa16(uint32_t s, const void* g) {
    asm volatile("cp.async.cg.shared.global [%0], [%1], 16;" :: "r"(s), "l"(g));
}
#define CP_COMMIT() asm volatile("cp.async.commit_group;" ::: "memory")
#define CP_WAIT(n)  asm volatile("cp.async.wait_group %0;" :: "n"(n) : "memory")

__device__ __forceinline__ void ldm_x4(uint32_t* r, uint32_t saddr) {
    asm volatile("ldmatrix.sync.aligned.m8n8.x4.shared.b16 {%0,%1,%2,%3}, [%4];"
        : "=r"(r[0]), "=r"(r[1]), "=r"(r[2]), "=r"(r[3]) : "r"(saddr));
}

__device__ __forceinline__ void mma16816_f16(uint32_t* c, const uint32_t* a,
                                             uint32_t b0, uint32_t b1) {
    asm volatile(
        "mma.sync.aligned.m16n8k16.row.col.f16.f16.f16.f16 "
        "{%0,%1},{%2,%3,%4,%5},{%6,%7},{%0,%1};"
        : "+r"(c[0]), "+r"(c[1])
        : "r"(a[0]), "r"(a[1]), "r"(a[2]), "r"(a[3]), "r"(b0), "r"(b1));
}

__device__ __forceinline__ uint32_t packh2(float a, float b) {
    __half2 h = __floats2half2_rn(a, b);
    return *(uint32_t*)&h;
}

// ===========================================================================
// Scratch
// ===========================================================================
__device__ __half g_wq [(size_t)CH * Cc];
__device__ __half g_wkv[(size_t)2 * CH * CTXD];
__device__ __half g_wo [(size_t)Cc * CH];
__device__ __half g_xnT [(size_t)Nn * Ss * Cc];       // [n][s][c]
__device__ __half g_ctxT[(size_t)Nn * Ss * CTXD];     // [n][s][d]
__device__ __half g_q  [(size_t)Nn * Ss * CH];        // [n][s][h*512+c]
__device__ __half g_k  [(size_t)Nn * Ss * CH];        // [n][s][h*512+c]
__device__ __half g_vb [(size_t)Nn * CH * Ss];        // [n][o][s]
__device__ __half g_attp[(size_t)Nn * Hh * Ss * Ss];  // exp(scores)
__device__ float  g_rowsum[ZTOT];
__device__ __half g_yT [(size_t)Nn * Ss * CH];        // [n][s][h*512+c]
__device__ float g_part[Nn * 128 * 2];
__device__ float g_stats[Nn * 2];

// ===========================================================================
// LayerNorm stats + misc prep
// ===========================================================================
__global__ void ln_part_kernel(const float* __restrict__ x) {
    int n = blockIdx.y, b = blockIdx.x;
    const int chunk = (Cc * Ss) / 128;
    const float4* p4 = (const float4*)(x + (size_t)n * Cc * Ss + (size_t)b * chunk);
    float s = 0.f, s2 = 0.f;
    for (int i = threadIdx.x; i < chunk / 4; i += 256) {
        float4 v = p4[i];
        s  += v.x + v.y + v.z + v.w;
        s2 += v.x * v.x + v.y * v.y + v.z * v.z + v.w * v.w;
    }
    __shared__ float sh0[256], sh1[256];
    sh0[threadIdx.x] = s; sh1[threadIdx.x] = s2;
    __syncthreads();
    for (int o = 128; o > 0; o >>= 1) {
        if (threadIdx.x < o) {
            sh0[threadIdx.x] += sh0[threadIdx.x + o];
            sh1[threadIdx.x] += sh1[threadIdx.x + o];
        }
        __syncthreads();
    }
    if (threadIdx.x == 0) {
        g_part[(n * 128 + b) * 2 + 0] = sh0[0];
        g_part[(n * 128 + b) * 2 + 1] = sh1[0];
    }
}

__global__ void ln_fin_kernel() {
    int n = blockIdx.x, t = threadIdx.x;
    float s  = g_part[(n * 128 + t) * 2 + 0];
    float s2 = g_part[(n * 128 + t) * 2 + 1];
    __shared__ float sh0[128], sh1[128];
    sh0[t] = s; sh1[t] = s2;
    __syncthreads();
    for (int o = 64; o > 0; o >>= 1) {
        if (t < o) { sh0[t] += sh0[t + o]; sh1[t] += sh1[t + o]; }
        __syncthreads();
    }
    if (t == 0) {
        const float inv = 1.0f / (float)(Cc * Ss);
        float mu  = sh0[0] * inv;
        float var = sh1[0] * inv - mu * mu;
        g_stats[n * 2 + 0] = mu;
        g_stats[n * 2 + 1] = rsqrtf(var + LNEPS);
    }
}

__global__ void zero_rowsum_kernel() {
    int i = blockIdx.x * 256 + threadIdx.x;
    ((float4*)g_rowsum)[i] = make_float4(0.f, 0.f, 0.f, 0.f);
}

// out = input + bo[row] (split-K out GEMM accumulates on top)
__global__ void init_out_kernel(const float* __restrict__ input,
                                const float* __restrict__ bo,
                                float* __restrict__ out) {
    int i = blockIdx.x * 256 + threadIdx.x;     // 4096 blocks -> 1M float4
    float4 v = ((const float4*)input)[i];
    float b = bo[(i >> 9) & 511];               // (i*4 / 2048) % 512
    v.x += b; v.y += b; v.z += b; v.w += b;
    ((float4*)out)[i] = v;
}

template<bool LN>
__global__ void prepT_kernel(const float* __restrict__ X, __half* __restrict__ O,
                             const float* __restrict__ gamma, const float* __restrict__ beta,
                             int R, int S)
{
    __shared__ float tile[32][33];
    int z = blockIdx.z;
    int s0 = blockIdx.x * 32, r0 = blockIdx.y * 32;
    const float* Xb = X + (size_t)z * R * S;
    __half* Ob = O + (size_t)z * R * S;
    float mu = 0.f, rs = 0.f;
    if (LN) { mu = g_stats[z * 2 + 0]; rs = g_stats[z * 2 + 1]; }
    int tx = threadIdx.x, ty = threadIdx.y;
#pragma unroll
    for (int i = 0; i < 32; i += 8) {
        int r = r0 + ty + i;
        float val = Xb[(size_t)r * S + s0 + tx];
        if (LN) {
            float g = gamma[r] * rs;
            val = val * g + (beta[r] - mu * g);
        }
        tile[ty + i][tx] = val;
    }
    __syncthreads();
#pragma unroll
    for (int i = 0; i < 32; i += 8) {
        int s = s0 + ty + i;
        Ob[(size_t)s * R + r0 + tx] = __float2half_rn(tile[tx][ty + i]);
    }
}

// Merged fp32->fp16 conversion of all three weight tensors (one launch).
__global__ void f2h3_kernel(const float* __restrict__ X0, __half* __restrict__ O0,
                            const float* __restrict__ X1, __half* __restrict__ O1,
                            const float* __restrict__ X2, __half* __restrict__ O2)
{
    int b = blockIdx.x;
    const float* X; __half* O; int i;
    if (b < 2048)      { X = X0; O = O0; i = b * 256 + threadIdx.x; }
    else if (b < 6144) { X = X1; O = O1; i = (b - 2048) * 256 + threadIdx.x; }
    else               { X = X2; O = O2; i = (b - 6144) * 256 + threadIdx.x; }
    float4 v = ((const float4*)X)[i];
    __half2* o = (__half2*)O + (size_t)i * 2;
    o[0] = __floats2half2_rn(v.x, v.y);
    o[1] = __floats2half2_rn(v.z, v.w);
}

// ===========================================================================
// 128x128 fp16-acc GEMM: 64x32 warp tiles, BK=32, 3-stage single-sync,
// __launch_bounds__(256,3) -> 3 CTAs/SM = 24 warps (R15 winning config).
// A: [M][K] K-major. B: [N][K] K-major.
// EPI 0: exp(d*SCALE2) fp16 -> attp[z][m][j] + rowsums (zn=z>>3, zh=z&7)
// EPI 1: row-bias fp16   -> vb [z][m][j]             (V; z = n)
// EPI 2: MERGED Q/K (z in [0,8): sel=z>>2, n=z&3): col-bias fp16
//        -> (sel? Cv2 : Cv)[n][s][4096col]
// EPI 3: /rowsum[m] fp16 -> yT [zn][m][zh*512+col]   (y; zn=z>>3, zh=z&7)
// EPI 5: SPLIT-K out: zn=z>>3 (n), zh=z&7 (k-slice via aSH/bSH=512);
//        fp32 atomicAdd into out[zn][m][j] (pre-initialized with input+bo)
// ===========================================================================
#define ROWB   80
#define STG128 20480     // (128 + 128) * 80
#define SMEM_C 61440     // 3 stages

template<int EPI>
__global__ __launch_bounds__(256, 3) void hg128(
    const __half* __restrict__ A, size_t lda, size_t aSN, size_t aSH,
    const __half* __restrict__ B, size_t ldb, size_t bSN, size_t bSH,
    void* __restrict__ Cv,
    const float* __restrict__ bias,
    const __half* __restrict__ A2, const __half* __restrict__ B2,
    const float* __restrict__ bias2, void* __restrict__ Cv2,
    float* __restrict__ rsum,
    int nt)
{
    extern __shared__ __align__(1024) char smem[];
    const uint32_t sb = smem_to_u32(smem);

    const int tid  = threadIdx.x;
    const int warp = tid >> 5;
    const int lane = tid & 31;
    const int wm = warp >> 2;       // 0..1
    const int wn = warp & 3;        // 0..3
    const int z  = blockIdx.z;
    const int m0 = blockIdx.y * 128;
    const int j0 = blockIdx.x * 128;

    // batch decode (+ Q/K merge for EPI 2)
    const __half* Abase = A;
    const __half* Bbase = B;
    const float*  biasp = bias;
    void*         Cp    = Cv;
    int zn, zh;
    if (EPI == 2) {
        zn = 0; zh = z & 3;
        if (z >> 2) { Abase = A2; Bbase = B2; biasp = bias2; Cp = Cv2; }
    } else if (EPI == 0 || EPI == 3 || EPI == 5) {
        zn = z >> 3; zh = z & 7;
    } else {
        zn = 0; zh = z;
    }

    const __half* Ab = Abase + (size_t)zn * aSN + (size_t)zh * aSH
                             + (size_t)(m0 + (tid >> 1)) * lda;
    const __half* Bb = Bbase + (size_t)zn * bSN + (size_t)zh * bSH
                             + (size_t)(j0 + (tid >> 1)) * ldb;

    const uint32_t sA = sb + (uint32_t)(tid >> 1) * ROWB + (uint32_t)(tid & 1) * 32;
    const uint32_t sB = sA + 10240;
    const int gseg = (tid & 1) * 16;

    auto prefetch = [&](int kt, int buf) {
        uint32_t so = (uint32_t)buf * STG128;
        const __half* ga = Ab + (size_t)kt * 32 + gseg;
        const __half* gb = Bb + (size_t)kt * 32 + gseg;
        cpa16(sA + so,      ga);
        cpa16(sA + so + 16, ga + 8);
        cpa16(sB + so,      gb);
        cpa16(sB + so + 16, gb + 8);
    };

    uint32_t acch[4][4][2];
#pragma unroll
    for (int i = 0; i < 4; i++)
#pragma unroll
        for (int j = 0; j < 4; j++) { acch[i][j][0] = 0u; acch[i][j][1] = 0u; }

    const int lrow = lane & 15;
    const int lcolb = (lane >> 4) * 16;

    prefetch(0, 0); CP_COMMIT();
    if (nt > 1) { prefetch(1, 1); CP_COMMIT(); }

    for (int t = 0; t < nt; t++) {
        if (t + 1 < nt) { CP_WAIT(1); } else { CP_WAIT(0); }
        __syncthreads();
        if (t + 2 < nt) { prefetch(t + 2, (t + 2) % 3); CP_COMMIT(); }

        uint32_t aB = sb + (uint32_t)((t % 3) * STG128);
        uint32_t bB = aB + 10240;
#pragma unroll
        for (int ks = 0; ks < 2; ks++) {
            uint32_t colb = (uint32_t)(ks * 32 + lcolb);
            uint32_t a[4][4], bf[2][4];
#pragma unroll
            for (int i = 0; i < 4; i++)
                ldm_x4(a[i], aB + (uint32_t)(wm * 64 + i * 16 + lrow) * ROWB + colb);
#pragma unroll
            for (int p = 0; p < 2; p++)
                ldm_x4(bf[p], bB + (uint32_t)(wn * 32 + p * 16 + lrow) * ROWB + colb);
#pragma unroll
            for (int i = 0; i < 4; i++) {
#pragma unroll
                for (int p = 0; p < 2; p++) {
                    mma16816_f16(acch[i][p * 2 + 0], a[i], bf[p][0], bf[p][2]);
                    mma16816_f16(acch[i][p * 2 + 1], a[i], bf[p][1], bf[p][3]);
                }
            }
        }
    }

    const int rq = lane >> 2;
    const int cq = (lane & 3) * 2;

#pragma unroll
    for (int i = 0; i < 4; i++) {
        const int ra = m0 + wm * 64 + i * 16 + rq;

        if (EPI == 0) {          // exp + rowsum -> attp [z][m][j]
            __half* d0 = (__half*)Cp + (size_t)z * Ss * Ss + (size_t)ra * Ss + j0;
            __half* d1 = d0 + 8 * Ss;
            float s0 = 0.f, s1 = 0.f;
#pragma unroll
            for (int j = 0; j < 4; j++) {
                int col = wn * 32 + (j >> 1) * 16 + (j & 1) * 8 + cq;
                float2 v0 = __half22float2(*(const __half2*)&acch[i][j][0]);
                float2 v1 = __half22float2(*(const __half2*)&acch[i][j][1]);
                float e0 = __expf(v0.x * SCALE2), e1 = __expf(v0.y * SCALE2);
                float e2 = __expf(v1.x * SCALE2), e3 = __expf(v1.y * SCALE2);
                s0 += e0 + e1; s1 += e2 + e3;
                *(uint32_t*)(d0 + col) = packh2(e0, e1);
                *(uint32_t*)(d1 + col) = packh2(e2, e3);
            }
            s0 += __shfl_xor_sync(0xFFFFFFFF, s0, 1);
            s0 += __shfl_xor_sync(0xFFFFFFFF, s0, 2);
            s1 += __shfl_xor_sync(0xFFFFFFFF, s1, 1);
            s1 += __shfl_xor_sync(0xFFFFFFFF, s1, 2);
            if ((lane & 3) == 0) {
                atomicAdd(rsum + (size_t)z * Ss + ra,     s0);
                atomicAdd(rsum + (size_t)z * Ss + ra + 8, s1);
            }
        } else if (EPI == 1) {   // V: row bias -> vb [z][m][j]
            float b0 = biasp[ra], b1 = biasp[ra + 8];
            __half* d0 = (__half*)Cp + (size_t)zh * CH * Ss + (size_t)ra * Ss + j0;
            __half* d1 = d0 + 8 * Ss;
#pragma unroll
            for (int j = 0; j < 4; j++) {
                int col = wn * 32 + (j >> 1) * 16 + (j & 1) * 8 + cq;
                float2 v0 = __half22float2(*(const __half2*)&acch[i][j][0]);
                float2 v1 = __half22float2(*(const __half2*)&acch[i][j][1]);
                *(uint32_t*)(d0 + col) = packh2(v0.x + b0, v0.y + b0);
                *(uint32_t*)(d1 + col) = packh2(v1.x + b1, v1.y + b1);
            }
        } else if (EPI == 2) {   // merged Q/K: col bias -> [n][s][4096]
            __half* d0 = (__half*)Cp + (size_t)zh * Ss * CH + (size_t)ra * CH + j0;
            __half* d1 = d0 + 8 * CH;
#pragma unroll
            for (int j = 0; j < 4; j++) {
                int col = wn * 32 + (j >> 1) * 16 + (j & 1) * 8 + cq;
                float2 bb = *(const float2*)&biasp[j0 + col];
                float2 v0 = __half22float2(*(const __half2*)&acch[i][j][0]);
                float2 v1 = __half22float2(*(const __half2*)&acch[i][j][1]);
                *(uint32_t*)(d0 + col) = packh2(v0.x + bb.x, v0.y + bb.y);
                *(uint32_t*)(d1 + col) = packh2(v1.x + bb.x, v1.y + bb.y);
            }
        } else if (EPI == 3) {   // y: /rowsum -> yT [zn][m][zh*512+col]
            float inv0 = 1.0f / rsum[(size_t)z * Ss + ra];
            float inv1 = 1.0f / rsum[(size_t)z * Ss + ra + 8];
            __half* d0 = (__half*)Cp + (size_t)zn * Ss * CH + (size_t)ra * CH + zh * 512 + j0;
            __half* d1 = d0 + 8 * CH;
#pragma unroll
            for (int j = 0; j < 4; j++) {
                int col = wn * 32 + (j >> 1) * 16 + (j & 1) * 8 + cq;
                float2 v0 = __half22float2(*(const __half2*)&acch[i][j][0]);
                float2 v1 = __half22float2(*(const __half2*)&acch[i][j][1]);
                *(uint32_t*)(d0 + col) = packh2(v0.x * inv0, v0.y * inv0);
                *(uint32_t*)(d1 + col) = packh2(v1.x * inv1, v1.y * inv1);
            }
        } else {                 // EPI 5: split-K out, fp32 atomicAdd
            float* dst = (float*)Cp;
            size_t off0 = (size_t)zn * Cc * Ss + (size_t)ra * Ss + j0;
            size_t off1 = off0 + 8 * Ss;
#pragma unroll
            for (int j = 0; j < 4; j++) {
                int col = wn * 32 + (j >> 1) * 16 + (j & 1) * 8 + cq;
                float2 v0 = __half22float2(*(const __half2*)&acch[i][j][0]);
                float2 v1 = __half22float2(*(const __half2*)&acch[i][j][1]);
                atomicAdd(dst + off0 + col,     v0.x);
                atomicAdd(dst + off0 + col + 1, v0.y);
                atomicAdd(dst + off1 + col,     v1.x);
                atomicAdd(dst + off1 + col + 1, v1.y);
            }
        }
    }
}

// ===========================================================================
// Host
// ===========================================================================
extern "C" void kernel_launch(void* const* d_in, const int* in_sizes, int n_in,
                              void* d_out, int out_size) {
    const float* input   = (const float*)d_in[0];
    const float* context = (const float*)d_in[1];
    const float* gamma   = (const float*)d_in[2];
    const float* beta    = (const float*)d_in[3];
    const float* Wq      = (const float*)d_in[4];
    const float* bq      = (const float*)d_in[5];
    const float* Wkv     = (const float*)d_in[6];
    const float* bkv     = (const float*)d_in[7];
    const float* Wo      = (const float*)d_in[8];
    const float* bo      = (const float*)d_in[9];
    float* out = (float*)d_out;

    static int configured = 0;
    if (!configured) {
        cudaFuncSetAttribute(hg128<0>, cudaFuncAttributeMaxDynamicSharedMemorySize, SMEM_C);
        cudaFuncSetAttribute(hg128<1>, cudaFuncAttributeMaxDynamicSharedMemorySize, SMEM_C);
        cudaFuncSetAttribute(hg128<2>, cudaFuncAttributeMaxDynamicSharedMemorySize, SMEM_C);
        cudaFuncSetAttribute(hg128<3>, cudaFuncAttributeMaxDynamicSharedMemorySize, SMEM_C);
        cudaFuncSetAttribute(hg128<5>, cudaFuncAttributeMaxDynamicSharedMemorySize, SMEM_C);
        configured = 1;
    }

    __half *wq_h, *wkv_h, *wo_h, *xnT, *ctxT, *qp, *kp, *vb, *attp, *yT;
    float *rsum;
    cudaGetSymbolAddress((void**)&wq_h,  g_wq);
    cudaGetSymbolAddress((void**)&wkv_h, g_wkv);
    cudaGetSymbolAddress((void**)&wo_h,  g_wo);
    cudaGetSymbolAddress((void**)&xnT,   g_xnT);
    cudaGetSymbolAddress((void**)&ctxT,  g_ctxT);
    cudaGetSymbolAddress((void**)&qp,    g_q);
    cudaGetSymbolAddress((void**)&kp,    g_k);
    cudaGetSymbolAddress((void**)&vb,    g_vb);
    cudaGetSymbolAddress((void**)&attp,  g_attp);
    cudaGetSymbolAddress((void**)&rsum,  g_rowsum);
    cudaGetSymbolAddress((void**)&yT,    g_yT);

    // 0: merged weight conversion
    f2h3_kernel<<<8192, 256>>>(Wq, wq_h, Wkv, wkv_h, Wo, wo_h);
    // 1: context transpose
    prepT_kernel<false><<<dim3(Ss / 32, CTXD / 32, Nn), dim3(32, 8)>>>(
        context, ctxT, nullptr, nullptr, CTXD, Ss);
    // 2: LN partials
    ln_part_kernel<<<dim3(128, Nn), 256>>>(input);

    // 3 (PROFILED): V = Wv @ ctx + bv -> vb [n][o][s]
    hg128<1><<<dim3(Ss / 128, CH / 128, Nn), 256, SMEM_C>>>(
        wkv_h + (size_t)CH * CTXD, CTXD, 0, 0,
        ctxT, CTXD, 0, (size_t)Ss * CTXD,
        vb, bkv + CH,
        nullptr, nullptr, nullptr, nullptr, nullptr, CTXD / 32);

    ln_fin_kernel<<<Nn, 128>>>();
    prepT_kernel<true><<<dim3(Ss / 32, Cc / 32, Nn), dim3(32, 8)>>>(
        input, xnT, gamma, beta, Cc, Ss);
    zero_rowsum_kernel<<<64, 256>>>();
    init_out_kernel<<<4096, 256>>>(input, bo, out);

    // merged Q + K projections: z in [0,4) -> Q, z in [4,8) -> K
    hg128<2><<<dim3(CH / 128, Ss / 128, 2 * Nn), 256, SMEM_C>>>(
        xnT, Cc, 0, (size_t)Ss * Cc,
        wq_h, Cc, 0, 0,
        qp, bq,
        ctxT, wkv_h, bkv, kp,
        nullptr, Cc / 32);

    // scores: exp(q·k^T * SCALE2) -> attp[z][q][k] + rowsums
    hg128<0><<<dim3(Ss / 128, Ss / 128, Nn * Hh), 256, SMEM_C>>>(
        qp, CH, (size_t)Ss * CH, 512,
        kp, CH, (size_t)Ss * CH, 512,
        attp, nullptr,
        nullptr, nullptr, nullptr, nullptr, rsum, Cc / 32);

    // y = (attp @ v^T) / rowsum -> yT [n][s][h*512+c]
    hg128<3><<<dim3(Cc / 128, Ss / 128, Nn * Hh), 256, SMEM_C>>>(
        attp, Ss, (size_t)8 * Ss * Ss, (size_t)Ss * Ss,
        vb, Ss, (size_t)CH * Ss, (size_t)512 * Ss,
        yT, nullptr,
        nullptr, nullptr, nullptr, nullptr, rsum, Ss / 32);

    // out += Wo @ y  (split-K=8; z = n*8 + kslice; each slice covers k=512)
    hg128<5><<<dim3(Ss / 128, Cc / 128, Nn * 8), 256, SMEM_C>>>(
        wo_h, CH, 0, 512,
        yT, CH, (size_t)Ss * CH, 512,
        out, nullptr,
        nullptr, nullptr, nullptr, nullptr, nullptr, 512 / 32);
}